// round 5
// baseline (speedup 1.0000x reference)
#include <cuda_runtime.h>

// ForwardKinematicsLayer — SMPL 24-joint FK, batch = 262144.
//
// Inputs (metadata order):
//   d_in[0] local_rots : f32 [B, 24, 3, 3]   (B*216 elements)
//   d_in[1] root_pos   : f32 [B, 3]
//   d_in[2] offsets    : f32 [24, 3]
// Output (tuple flattened in reference return order):
//   d_out[0 .. B*72)        global_pos : f32 [B, 24, 3]
//   d_out[B*72 .. B*288)    global_rots: f32 [B, 24, 3, 3]

#define NJ   24
#define TPB  128
#define RPAD 217   // 216 rot floats per item, odd stride -> conflict-free LDS/STS
#define PPAD 73    // 72 pos floats per item, odd stride

__device__ __constant__ int d_dummy; // (unused; keeps toolchain happy)

static __device__ __forceinline__ int par_of(int j) {
    // compile-time folded when j is a constant (loop fully unrolled)
    constexpr int kPar[NJ] = {-1, 0, 0, 0, 1, 2, 3, 4, 5, 6, 7, 8,
                               9, 9, 9, 12, 13, 14, 16, 17, 18, 19, 20, 21};
    return kPar[j];
}

__global__ void __launch_bounds__(TPB)
fk_kernel(const float* __restrict__ lrots,   // [B,24,3,3]
          const float* __restrict__ rootp,   // [B,3]
          const float* __restrict__ offs,    // [24,3]
          float* __restrict__ out,           // [B*72 | B*216]
          int batch)
{
    extern __shared__ float sm[];            // TPB * RPAD floats

    const int tid = threadIdx.x;
    const long long base_item = (long long)blockIdx.x * TPB;

    const float* in_rot  = lrots + base_item * 216;
    float*       out_pos = out;
    float*       out_rot = out + (long long)batch * 72;

    // ---------------- Phase 1: coalesced gmem -> smem (local rots) ----------
    // idx = k*TPB + tid is consecutive across the warp -> fully coalesced LDG.
    // smem addr item*RPAD + e is also consecutive across the warp -> no STS conflicts.
#pragma unroll 4
    for (int k = 0; k < 216; ++k) {
        int idx  = k * TPB + tid;
        int item = idx / 216;
        int e    = idx - item * 216;
        sm[item * RPAD + e] = in_rot[idx];
    }
    __syncthreads();

    // ---------------- Phase 2: FK chain (one thread per item) ---------------
    {
        float* my = sm + tid * RPAD;         // this item's 24 rot slots
        float P[NJ][3];                      // positions in registers

        const long long b = base_item + tid;
        P[0][0] = rootp[b * 3 + 0];
        P[0][1] = rootp[b * 3 + 1];
        P[0][2] = rootp[b * 3 + 2];
        // joint 0: global rot == local rot -> already in smem slot 0 (no-op)

#pragma unroll
        for (int j = 1; j < NJ; ++j) {
            const int p = par_of(j);

            float Gp[9], L[9];
#pragma unroll
            for (int c = 0; c < 9; ++c) Gp[c] = my[p * 9 + c];
#pragma unroll
            for (int c = 0; c < 9; ++c) L[c]  = my[j * 9 + c];

            const float o0 = __ldg(&offs[j * 3 + 0]);
            const float o1 = __ldg(&offs[j * 3 + 1]);
            const float o2 = __ldg(&offs[j * 3 + 2]);

            // position: P[j] = P[p] + Gp @ off[j]
#pragma unroll
            for (int i = 0; i < 3; ++i) {
                P[j][i] = P[p][i]
                        + Gp[i * 3 + 0] * o0
                        + Gp[i * 3 + 1] * o1
                        + Gp[i * 3 + 2] * o2;
            }
            // rotation: G[j] = Gp @ L[j], written back in place over L[j]
#pragma unroll
            for (int i = 0; i < 3; ++i) {
#pragma unroll
                for (int c = 0; c < 3; ++c) {
                    my[j * 9 + i * 3 + c] =
                          Gp[i * 3 + 0] * L[0 * 3 + c]
                        + Gp[i * 3 + 1] * L[1 * 3 + c]
                        + Gp[i * 3 + 2] * L[2 * 3 + c];
                }
            }
        }
        __syncthreads();

        // -------------- Phase 3: coalesced smem -> gmem (global rots) -------
        const long long rot_base = base_item * 216;
#pragma unroll 4
        for (int k = 0; k < 216; ++k) {
            int idx  = k * TPB + tid;
            int item = idx / 216;
            int e    = idx - item * 216;
            out_rot[rot_base + idx] = sm[item * RPAD + e];
        }
        __syncthreads();

        // -------------- Phase 4: positions registers -> smem (reuse buffer) -
#pragma unroll
        for (int j = 0; j < NJ; ++j) {
#pragma unroll
            for (int c = 0; c < 3; ++c) {
                sm[tid * PPAD + j * 3 + c] = P[j][c];
            }
        }
    }
    __syncthreads();

    // ---------------- Phase 5: coalesced smem -> gmem (positions) -----------
    const long long pos_base = base_item * 72;
#pragma unroll 4
    for (int k = 0; k < 72; ++k) {
        int idx  = k * TPB + tid;
        int item = idx / 72;
        int e    = idx - item * 72;
        out_pos[pos_base + idx] = sm[item * PPAD + e];
    }
}

extern "C" void kernel_launch(void* const* d_in, const int* in_sizes, int n_in,
                              void* d_out, int out_size)
{
    const float* lrots = (const float*)d_in[0];
    const float* rootp = (const float*)d_in[1];
    const float* offs  = (const float*)d_in[2];
    float*       out   = (float*)d_out;

    const int batch = in_sizes[0] / 216;       // B = 262144
    const int grid  = batch / TPB;             // exact: 262144 / 128 = 2048
    const int smem  = TPB * RPAD * (int)sizeof(float);  // 111,104 B

    // Opt into >48KB dynamic smem (idempotent, capture-safe host call).
    cudaFuncSetAttribute(fk_kernel,
                         cudaFuncAttributeMaxDynamicSharedMemorySize, smem);

    fk_kernel<<<grid, TPB, smem>>>(lrots, rootp, offs, out, batch);
}

// round 6
// speedup vs baseline: 2.4366x; 2.4366x over previous
#include <cuda_runtime.h>

// ForwardKinematicsLayer — SMPL 24-joint FK, batch = 262144.
//
// Inputs (metadata order):
//   d_in[0] local_rots : f32 [B, 24, 3, 3]   (B*216 elements)
//   d_in[1] root_pos   : f32 [B, 3]
//   d_in[2] offsets    : f32 [24, 3]
// Output (tuple flattened in reference return order):
//   d_out[0 .. B*72)        global_pos : f32 [B, 24, 3]
//   d_out[B*72 .. B*288)    global_rots: f32 [B, 24, 3, 3]
//
// R5 design: 128 threads stage 64 items (smem 55.5KB -> 4 CTAs/SM = 16 warps),
// deep-unrolled coalesced gmem<->smem phases for MLP, odd smem strides
// (217 / 73) keep every scalar smem access bank-conflict-free.

#define NJ     24
#define TPB    128
#define ITEMS  64            // items staged per block (TPB/2)
#define RPAD   217           // 216 rot floats per item + 1 pad (odd stride)
#define PPAD   73            // 72 pos floats per item + 1 pad (odd stride)

static __device__ __forceinline__ int par_of(int j) {
    constexpr int kPar[NJ] = {-1, 0, 0, 0, 1, 2, 3, 4, 5, 6, 7, 8,
                               9, 9, 9, 12, 13, 14, 16, 17, 18, 19, 20, 21};
    return kPar[j];
}

__global__ void __launch_bounds__(TPB, 4)
fk_kernel(const float* __restrict__ lrots,   // [B,24,3,3]
          const float* __restrict__ rootp,   // [B,3]
          const float* __restrict__ offs,    // [24,3]
          float* __restrict__ out,           // [B*72 pos | B*216 rot]
          int batch)
{
    extern __shared__ float sm[];            // ITEMS * RPAD floats (13888)
    __shared__ float soffs[NJ * 3];          // bone offsets, broadcast reads

    const int tid = threadIdx.x;
    const long long base_item = (long long)blockIdx.x * ITEMS;

    const float* in_rot  = lrots + base_item * 216;
    float*       out_pos = out;
    float*       out_rot = out + (long long)batch * 72;

    if (tid < NJ * 3) soffs[tid] = offs[tid];

    // ---------------- Phase 1: coalesced gmem -> smem (local rots) ----------
    // 64*216/128 = 108 iterations; unroll 27 => ~27 independent LDGs in
    // flight per warp (the MLP that saturates HBM).
#pragma unroll 27
    for (int k = 0; k < (ITEMS * 216) / TPB; ++k) {
        int idx  = k * TPB + tid;
        int item = idx / 216;
        int e    = idx - item * 216;
        sm[item * RPAD + e] = in_rot[idx];
    }
    __syncthreads();

    // ---------------- Phase 2: FK chain (threads 0..63, one per item) -------
    float P[NJ][3];                          // positions live across barriers
    if (tid < ITEMS) {
        float* my = sm + tid * RPAD;         // this item's 24 rot slots

        const long long b = base_item + tid;
        P[0][0] = rootp[b * 3 + 0];
        P[0][1] = rootp[b * 3 + 1];
        P[0][2] = rootp[b * 3 + 2];
        // joint 0: global rot == local rot (already in slot 0)

#pragma unroll
        for (int j = 1; j < NJ; ++j) {
            const int p = par_of(j);

            float Gp[9], L[9];
#pragma unroll
            for (int c = 0; c < 9; ++c) Gp[c] = my[p * 9 + c];
#pragma unroll
            for (int c = 0; c < 9; ++c) L[c]  = my[j * 9 + c];

            const float o0 = soffs[j * 3 + 0];
            const float o1 = soffs[j * 3 + 1];
            const float o2 = soffs[j * 3 + 2];

#pragma unroll
            for (int i = 0; i < 3; ++i) {
                P[j][i] = P[p][i]
                        + Gp[i * 3 + 0] * o0
                        + Gp[i * 3 + 1] * o1
                        + Gp[i * 3 + 2] * o2;
            }
#pragma unroll
            for (int i = 0; i < 3; ++i) {
#pragma unroll
                for (int c = 0; c < 3; ++c) {
                    my[j * 9 + i * 3 + c] =
                          Gp[i * 3 + 0] * L[0 * 3 + c]
                        + Gp[i * 3 + 1] * L[1 * 3 + c]
                        + Gp[i * 3 + 2] * L[2 * 3 + c];
                }
            }
        }
    }
    __syncthreads();

    // ---------------- Phase 3: coalesced smem -> gmem (global rots) ---------
    {
        const long long rot_base = base_item * 216;
#pragma unroll 27
        for (int k = 0; k < (ITEMS * 216) / TPB; ++k) {
            int idx  = k * TPB + tid;
            int item = idx / 216;
            int e    = idx - item * 216;
            out_rot[rot_base + idx] = sm[item * RPAD + e];
        }
    }
    __syncthreads();

    // ---------------- Phase 4: positions regs -> smem (reuse buffer) --------
    if (tid < ITEMS) {
#pragma unroll
        for (int j = 0; j < NJ; ++j) {
#pragma unroll
            for (int c = 0; c < 3; ++c) {
                sm[tid * PPAD + j * 3 + c] = P[j][c];
            }
        }
    }
    __syncthreads();

    // ---------------- Phase 5: coalesced smem -> gmem (positions) -----------
    {
        const long long pos_base = base_item * 72;
#pragma unroll
        for (int k = 0; k < (ITEMS * 72) / TPB; ++k) {   // 36 iterations
            int idx  = k * TPB + tid;
            int item = idx / 72;
            int e    = idx - item * 72;
            out_pos[pos_base + idx] = sm[item * PPAD + e];
        }
    }
}

extern "C" void kernel_launch(void* const* d_in, const int* in_sizes, int n_in,
                              void* d_out, int out_size)
{
    const float* lrots = (const float*)d_in[0];
    const float* rootp = (const float*)d_in[1];
    const float* offs  = (const float*)d_in[2];
    float*       out   = (float*)d_out;

    const int batch = in_sizes[0] / 216;               // B = 262144
    const int grid  = batch / ITEMS;                   // 4096 blocks
    const int smem  = ITEMS * RPAD * (int)sizeof(float); // 55,552 B -> 4 CTAs/SM

    cudaFuncSetAttribute(fk_kernel,
                         cudaFuncAttributeMaxDynamicSharedMemorySize, smem);

    fk_kernel<<<grid, TPB, smem>>>(lrots, rootp, offs, out, batch);
}